// round 4
// baseline (speedup 1.0000x reference)
#include <cuda_runtime.h>
#include <cuda_bf16.h>
#include <cstdint>

#define B_  16
#define T_  512
#define H_  2048
#define TH_ (T_ * H_)        // 1048576
#define WLD 4096             // W row stride (floats)
#define NBLK 128

// ---------------- device globals -------------------------------------------
__device__ unsigned g_bar[T_];

__device__ __nv_bfloat16 g_xh[(size_t)B_ * T_ * H_];
__device__ __nv_bfloat16 g_xl[(size_t)B_ * T_ * H_];
__device__ __nv_bfloat16 g_wxh[(size_t)H_ * H_];
__device__ __nv_bfloat16 g_wxl[(size_t)H_ * H_];
__device__ __nv_bfloat16 g_whh[(size_t)H_ * H_];
__device__ __nv_bfloat16 g_whl[(size_t)H_ * H_];
// ping-pong split h buffers for the scan
__device__ __nv_bfloat16 g_hh2[2][B_ * H_];
__device__ __nv_bfloat16 g_hl2[2][B_ * H_];

__global__ void zero_bar_kernel() { g_bar[threadIdx.x] = 0u; }

// ---------------- helpers ---------------------------------------------------
__device__ __forceinline__ uint32_t smem_u32(const void* p) {
    return (uint32_t)__cvta_generic_to_shared(p);
}
__device__ __forceinline__ void cp16(uint32_t s, const void* g) {
    asm volatile("cp.async.cg.shared.global [%0], [%1], 16;" :: "r"(s), "l"(g));
}
#define CP_COMMIT() asm volatile("cp.async.commit_group;")

__device__ __forceinline__ void ldsm4(uint32_t (&r)[4], uint32_t addr) {
    asm volatile("ldmatrix.sync.aligned.m8n8.x4.shared.b16 {%0,%1,%2,%3}, [%4];"
                 : "=r"(r[0]), "=r"(r[1]), "=r"(r[2]), "=r"(r[3]) : "r"(addr));
}
__device__ __forceinline__ void mma16816(float (&c)[4], const uint32_t (&a)[4],
                                         uint32_t b0, uint32_t b1) {
    asm volatile("mma.sync.aligned.m16n8k16.row.col.f32.bf16.bf16.f32 "
                 "{%0,%1,%2,%3}, {%4,%5,%6,%7}, {%8,%9}, {%0,%1,%2,%3};"
                 : "+f"(c[0]), "+f"(c[1]), "+f"(c[2]), "+f"(c[3])
                 : "r"(a[0]), "r"(a[1]), "r"(a[2]), "r"(a[3]), "r"(b0), "r"(b1));
}

// ---------------- prepass: hi/lo bf16 splits --------------------------------
__global__ void split_x_kernel(const float* __restrict__ x) {
    size_t fi = (size_t)blockIdx.x * blockDim.x + threadIdx.x;
    if (fi >= (size_t)B_ * T_ * H_ / 4) return;
    float4 v = *(const float4*)(x + fi * 4);
    union { __nv_bfloat16 b[4]; uint2 u; } hh, ll;
    float f[4] = {v.x, v.y, v.z, v.w};
#pragma unroll
    for (int i = 0; i < 4; i++) {
        hh.b[i] = __float2bfloat16_rn(f[i]);
        ll.b[i] = __float2bfloat16_rn(f[i] - __bfloat162float(hh.b[i]));
    }
    *(uint2*)(g_xh + fi * 4) = hh.u;
    *(uint2*)(g_xl + fi * 4) = ll.u;
}

__global__ void split_w_kernel(const float* __restrict__ W) {
    size_t fi = (size_t)blockIdx.x * blockDim.x + threadIdx.x;
    if (fi >= (size_t)H_ * H_ / 4) return;
    int g = (int)(fi >> 9);
    int c = (int)(fi & 511) * 4;
    const float* base = W + (size_t)g * WLD;

    float4 v = *(const float4*)(base + c);
    union { __nv_bfloat16 b[4]; uint2 u; } hh, ll;
    float f[4] = {v.x, v.y, v.z, v.w};
#pragma unroll
    for (int i = 0; i < 4; i++) {
        hh.b[i] = __float2bfloat16_rn(f[i]);
        ll.b[i] = __float2bfloat16_rn(f[i] - __bfloat162float(hh.b[i]));
    }
    *(uint2*)(g_wxh + (size_t)g * H_ + c) = hh.u;
    *(uint2*)(g_wxl + (size_t)g * H_ + c) = ll.u;

    v = *(const float4*)(base + H_ + c);
    float f2[4] = {v.x, v.y, v.z, v.w};
#pragma unroll
    for (int i = 0; i < 4; i++) {
        hh.b[i] = __float2bfloat16_rn(f2[i]);
        ll.b[i] = __float2bfloat16_rn(f2[i] - __bfloat162float(hh.b[i]));
    }
    *(uint2*)(g_whh + (size_t)g * H_ + c) = hh.u;
    *(uint2*)(g_whl + (size_t)g * H_ + c) = ll.u;
}

// ===========================================================================
// Phase 1: u[m,g] = sum_k x[m,k] W[g,k] + b[g], 3x bf16 split mma.
// 128x128x32 tiles, 4-stage cp.async pipeline, single sync per iter.
// ===========================================================================
#define P1_ST 40
#define P1_TILE (128 * P1_ST)
#define P1_NS 4
#define P1_SMEM_BYTES (2 * P1_NS * P1_TILE * 2)   // 81920

__global__ __launch_bounds__(256, 2)
void gemm_u_mma(const float* __restrict__ bias, float* __restrict__ out)
{
    extern __shared__ __align__(16) __nv_bfloat16 sm[];
    __nv_bfloat16* As[P1_NS];
    __nv_bfloat16* Bs[P1_NS];
#pragma unroll
    for (int s = 0; s < P1_NS; s++) {
        As[s] = sm + s * P1_TILE;
        Bs[s] = sm + (P1_NS + s) * P1_TILE;
    }

    const int tid = threadIdx.x, lane = tid & 31, wid = tid >> 5;
    const int m0 = blockIdx.y * 128, g0 = blockIdx.x * 128;
    const int wm = wid & 3, wn = wid >> 2;

    const __nv_bfloat16* Ag[3] = { g_xh, g_xh, g_xl };
    const __nv_bfloat16* Bg[3] = { g_wxh, g_wxl, g_wxh };

    const int lrow = tid >> 1;
    const int lco  = (tid & 1) * 16;

    float acc[2][8][4];
#pragma unroll
    for (int i = 0; i < 2; i++)
#pragma unroll
        for (int j = 0; j < 8; j++)
#pragma unroll
            for (int q = 0; q < 4; q++) acc[i][j][q] = 0.0f;

#define P1_ISSUE(st, it) do {                                                  \
        int _p = (it) >> 6, _kk = ((it) & 63) * 32;                            \
        const __nv_bfloat16* _ga = Ag[_p] + (size_t)(m0 + lrow) * H_ + _kk + lco; \
        const __nv_bfloat16* _gb = Bg[_p] + (size_t)(g0 + lrow) * H_ + _kk + lco; \
        uint32_t _sa = smem_u32(As[st] + lrow * P1_ST + lco);                  \
        uint32_t _sb = smem_u32(Bs[st] + lrow * P1_ST + lco);                  \
        cp16(_sa, _ga); cp16(_sa + 16, _ga + 8);                               \
        cp16(_sb, _gb); cp16(_sb + 16, _gb + 8);                               \
    } while (0)

    P1_ISSUE(0, 0); CP_COMMIT();
    P1_ISSUE(1, 1); CP_COMMIT();
    P1_ISSUE(2, 2); CP_COMMIT();

    const int NT = 192;
    for (int it = 0; it < NT; ++it) {
        asm volatile("cp.async.wait_group 2;");
        __syncthreads();
        int nx = it + 3;
        if (nx < NT) { P1_ISSUE(nx & 3, nx); }
        CP_COMMIT();

        const __nv_bfloat16* A_s = As[it & 3];
        const __nv_bfloat16* B_s = Bs[it & 3];
#pragma unroll
        for (int kq = 0; kq < 2; kq++) {
            uint32_t a[2][4];
#pragma unroll
            for (int mt = 0; mt < 2; mt++)
                ldsm4(a[mt], smem_u32(A_s + (wm * 32 + mt * 16 + (lane & 15)) * P1_ST
                                          + kq * 16 + ((lane >> 4) << 3)));
            uint32_t bf[4][4];
#pragma unroll
            for (int ng = 0; ng < 4; ng++)
                ldsm4(bf[ng], smem_u32(B_s + (wn * 64 + ng * 16 + (lane & 7) + ((lane & 16) >> 1)) * P1_ST
                                           + kq * 16 + (lane & 8)));
#pragma unroll
            for (int mt = 0; mt < 2; mt++)
#pragma unroll
                for (int ng = 0; ng < 4; ng++) {
                    mma16816(acc[mt][2 * ng],     a[mt], bf[ng][0], bf[ng][1]);
                    mma16816(acc[mt][2 * ng + 1], a[mt], bf[ng][2], bf[ng][3]);
                }
        }
    }

    const int r0 = lane >> 2, c0 = (lane & 3) * 2;
#pragma unroll
    for (int mt = 0; mt < 2; mt++) {
        int m = m0 + wm * 32 + mt * 16 + r0;
#pragma unroll
        for (int nt = 0; nt < 8; nt++) {
            int g = g0 + wn * 64 + nt * 8 + c0;
            float bx = bias[g], by = bias[g + 1];
            float2 v0 = { acc[mt][nt][0] + bx, acc[mt][nt][1] + by };
            float2 v1 = { acc[mt][nt][2] + bx, acc[mt][nt][3] + by };
            *(float2*)(out + (size_t)m * H_ + g)       = v0;
            *(float2*)(out + (size_t)(m + 8) * H_ + g) = v1;
        }
    }
}

// ===========================================================================
// Phase 2: persistent scan, full-K blocks. Block gi owns g [gi*16, gi*16+16),
// all K=2048. Wh hi/lo (131 KB) resident in smem. h streamed as producer-
// split bf16 hi/lo via ping-pong global buffers, cp.async double-buffered
// in 4 chunks of 512 k. 8 warps k-split; smem reduction; NO global atomics.
// ===========================================================================
#define WST 2056                       // Wh smem row stride (bf16)
#define HST 520                        // h  smem row stride (bf16)
#define O_WHH 0
#define O_WHL (16 * WST)               // 32896
#define O_HH  (2 * 16 * WST)           // 65792
#define O_HL  (O_HH + 2 * 16 * HST)    // 82432
#define O_RED (O_HL + 2 * 16 * HST)    // 99072 (bf16 elems; fp32 area after)
#define SC_SMEM_BYTES (O_RED * 2 + 8 * 256 * 4)   // 198144 + 8192 = 206336

__global__ __launch_bounds__(256, 1)
void rnn_scan2(float* __restrict__ out)
{
    extern __shared__ __align__(16) __nv_bfloat16 sm[];
    __nv_bfloat16* whh_s = sm + O_WHH;
    __nv_bfloat16* whl_s = sm + O_WHL;
    __nv_bfloat16* hh_s  = sm + O_HH;
    __nv_bfloat16* hl_s  = sm + O_HL;
    float* red = (float*)(sm + O_RED);

    const int tid = threadIdx.x, lane = tid & 31, wid = tid >> 5;
    const int gi = blockIdx.x;
    const int g0 = gi * 16;

    // ---- stage Wh hi/lo slice: 16 rows x 2048 ----
    for (int i = tid; i < 16 * 256; i += 256) {
        int row = i >> 8;
        int c8  = (i & 255) * 8;
        *(uint4*)(whh_s + row * WST + c8) =
            *(const uint4*)(g_whh + (size_t)(g0 + row) * H_ + c8);
        *(uint4*)(whl_s + row * WST + c8) =
            *(const uint4*)(g_whl + (size_t)(g0 + row) * H_ + c8);
    }

    // ---- split h_0 (= u_0, already in out[:,0,:]) into g_hh2[0]/g_hl2[0] ----
    {
        int idx = gi * 256 + tid;            // 0..32767
        int b = idx >> 11, g = idx & 2047;
        float h = out[(size_t)b * TH_ + g];
        __nv_bfloat16 hi = __float2bfloat16_rn(h);
        __nv_bfloat16 lo = __float2bfloat16_rn(h - __bfloat162float(hi));
        g_hh2[0][b * H_ + g] = hi;
        g_hl2[0][b * H_ + g] = lo;
    }
    __threadfence();
    __syncthreads();
    if (tid == 0) {
        atomicAdd(&g_bar[0], 1u);
        volatile unsigned* p = &g_bar[0];
        while (*p < NBLK) { __nanosleep(32); }
        __threadfence();
    }
    __syncthreads();

    const int kw = wid * 64;                 // warp k-offset within a chunk
    const int r0 = lane >> 2, c0 = (lane & 3) * 2;
    const int ub = tid >> 4, ug = tid & 15;  // (b, g_local) ownership

    for (int t = 1; t < T_; ++t) {
        const int pb = (t - 1) & 1;
        const __nv_bfloat16* srcH = g_hh2[pb];
        const __nv_bfloat16* srcL = g_hl2[pb];

        // u prefetch (phase-1 value at out[:, t, g-slice]; overwritten below)
        float u = __ldg(out + (size_t)ub * TH_ + (size_t)t * H_ + g0 + ug);

#define H_ISSUE(c) do { int _cb = ((c) & 1) * (16 * HST);                      \
        _Pragma("unroll")                                                      \
        for (int _r = 0; _r < 4; _r++) {                                       \
            int _i = tid + _r * 256;                                           \
            int _row = _i >> 6; int _c8 = (_i & 63) * 8;                       \
            cp16(smem_u32(hh_s + _cb + _row * HST + _c8),                      \
                 srcH + (size_t)_row * H_ + (c) * 512 + _c8);                  \
            cp16(smem_u32(hl_s + _cb + _row * HST + _c8),                      \
                 srcL + (size_t)_row * H_ + (c) * 512 + _c8);                  \
        } } while (0)

        H_ISSUE(0); CP_COMMIT();

        float accA[2][4], accB[2][4];
#pragma unroll
        for (int i = 0; i < 2; i++)
#pragma unroll
            for (int q = 0; q < 4; q++) { accA[i][q] = 0.0f; accB[i][q] = 0.0f; }

        for (int c = 0; c < 4; c++) {
            if (c < 3) { H_ISSUE(c + 1); CP_COMMIT();
                         asm volatile("cp.async.wait_group 1;"); }
            else       { asm volatile("cp.async.wait_group 0;"); }
            __syncthreads();

            const __nv_bfloat16* hhb = hh_s + (c & 1) * (16 * HST);
            const __nv_bfloat16* hlb = hl_s + (c & 1) * (16 * HST);
            const uint32_t aH = smem_u32(hhb + (lane & 15) * HST + kw + ((lane >> 4) << 3));
            const uint32_t aL = smem_u32(hlb + (lane & 15) * HST + kw + ((lane >> 4) << 3));
            const int brow = (lane & 7) + ((lane & 16) >> 1);
            const uint32_t bH = smem_u32(whh_s + brow * WST + c * 512 + kw + (lane & 8));
            const uint32_t bL = smem_u32(whl_s + brow * WST + c * 512 + kw + (lane & 8));
#pragma unroll
            for (int kq = 0; kq < 4; kq++) {
                uint32_t ah[4], al[4], bh[4], bl[4];
                ldsm4(ah, aH + kq * 32);
                ldsm4(bh, bH + kq * 32);
                ldsm4(bl, bL + kq * 32);
                ldsm4(al, aL + kq * 32);
                float (*ac)[4] = (kq & 1) ? accB : accA;
                mma16816(ac[0], ah, bh[0], bh[1]);
                mma16816(ac[1], ah, bh[2], bh[3]);
                mma16816(ac[0], ah, bl[0], bl[1]);
                mma16816(ac[1], ah, bl[2], bl[3]);
                mma16816(ac[0], al, bh[0], bh[1]);
                mma16816(ac[1], al, bh[2], bh[3]);
            }
            __syncthreads();
        }

        // ---- per-warp partials -> smem ----
        float* rw = red + wid * 256;
#pragma unroll
        for (int nt = 0; nt < 2; nt++) {
            float2 v0 = { accA[nt][0] + accB[nt][0], accA[nt][1] + accB[nt][1] };
            float2 v1 = { accA[nt][2] + accB[nt][2], accA[nt][3] + accB[nt][3] };
            *(float2*)(rw + r0 * 16 + nt * 8 + c0)       = v0;
            *(float2*)(rw + (r0 + 8) * 16 + nt * 8 + c0) = v1;
        }
        __syncthreads();

        // ---- reduce 8 warps, add u, store fp32 + bf16 hi/lo ----
        float s = u;
#pragma unroll
        for (int w = 0; w < 8; w++) s += red[w * 256 + ub * 16 + ug];

        out[(size_t)ub * TH_ + (size_t)t * H_ + g0 + ug] = s;
        __nv_bfloat16 hi = __float2bfloat16_rn(s);
        __nv_bfloat16 lo = __float2bfloat16_rn(s - __bfloat162float(hi));
        const int wb = t & 1;
        g_hh2[wb][ub * H_ + g0 + ug] = hi;
        g_hl2[wb][ub * H_ + g0 + ug] = lo;

        // ---- global step barrier ----
        __threadfence();
        __syncthreads();
        if (t < T_ - 1) {
            if (tid == 0) {
                atomicAdd(&g_bar[t], 1u);
                volatile unsigned* p = &g_bar[t];
                while (*p < NBLK) { __nanosleep(32); }
                __threadfence();
            }
            __syncthreads();
        }
    }
}

// ---------------- h_last copy ----------------------------------------------
__global__ void hlast_kernel(const float* __restrict__ out,
                             float* __restrict__ hlast)
{
    int i = blockIdx.x * blockDim.x + threadIdx.x;
    if (i < B_ * H_) {
        int b = i / H_;
        int g = i % H_;
        hlast[i] = out[(size_t)b * TH_ + (size_t)(T_ - 1) * H_ + g];
    }
}

// ---------------- launch ----------------------------------------------------
extern "C" void kernel_launch(void* const* d_in, const int* in_sizes, int n_in,
                              void* d_out, int out_size)
{
    const float* x  = (const float*)d_in[0];
    const float* W  = (const float*)d_in[1];
    const float* bi = (const float*)d_in[2];
    float* out = (float*)d_out;

    cudaFuncSetAttribute(gemm_u_mma,
                         cudaFuncAttributeMaxDynamicSharedMemorySize,
                         P1_SMEM_BYTES);
    cudaFuncSetAttribute(rnn_scan2,
                         cudaFuncAttributeMaxDynamicSharedMemorySize,
                         SC_SMEM_BYTES);

    zero_bar_kernel<<<1, T_>>>();
    split_x_kernel<<<(B_ * T_ * H_ / 4 + 255) / 256, 256>>>(x);
    split_w_kernel<<<(H_ * H_ / 4 + 255) / 256, 256>>>(W);

    dim3 ggrid(H_ / 128, (B_ * T_) / 128);   // (16, 64)
    gemm_u_mma<<<ggrid, 256, P1_SMEM_BYTES>>>(bi, out);

    rnn_scan2<<<NBLK, 256, SC_SMEM_BYTES>>>(out);

    if (out_size >= B_ * T_ * H_ + B_ * H_) {
        hlast_kernel<<<(B_ * H_ + 255) / 256, 256>>>(out, out + (size_t)B_ * T_ * H_);
    }
}

// round 5
// speedup vs baseline: 1.2096x; 1.2096x over previous
#include <cuda_runtime.h>
#include <cuda_bf16.h>
#include <cstdint>

#define B_  16
#define T_  512
#define H_  2048
#define TH_ (T_ * H_)        // 1048576
#define WLD 4096             // W row stride (floats)
#define NBLK 128

// ---------------- device globals -------------------------------------------
__device__ unsigned g_bar[T_];

__device__ __nv_bfloat16 g_xh[(size_t)B_ * T_ * H_];
__device__ __nv_bfloat16 g_xl[(size_t)B_ * T_ * H_];
__device__ __nv_bfloat16 g_wxh[(size_t)H_ * H_];
__device__ __nv_bfloat16 g_wxl[(size_t)H_ * H_];
__device__ __nv_bfloat16 g_whh[(size_t)H_ * H_];
__device__ __nv_bfloat16 g_whl[(size_t)H_ * H_];

__global__ void zero_bar_kernel() { g_bar[threadIdx.x] = 0u; }

// ---------------- helpers ---------------------------------------------------
__device__ __forceinline__ uint32_t smem_u32(const void* p) {
    return (uint32_t)__cvta_generic_to_shared(p);
}
__device__ __forceinline__ void cp16(uint32_t s, const void* g) {
    asm volatile("cp.async.cg.shared.global [%0], [%1], 16;" :: "r"(s), "l"(g));
}
#define CP_COMMIT() asm volatile("cp.async.commit_group;")

__device__ __forceinline__ void ldsm4(uint32_t (&r)[4], uint32_t addr) {
    asm volatile("ldmatrix.sync.aligned.m8n8.x4.shared.b16 {%0,%1,%2,%3}, [%4];"
                 : "=r"(r[0]), "=r"(r[1]), "=r"(r[2]), "=r"(r[3]) : "r"(addr));
}
__device__ __forceinline__ void mma16816(float (&c)[4], const uint32_t (&a)[4],
                                         uint32_t b0, uint32_t b1) {
    asm volatile("mma.sync.aligned.m16n8k16.row.col.f32.bf16.bf16.f32 "
                 "{%0,%1,%2,%3}, {%4,%5,%6,%7}, {%8,%9}, {%0,%1,%2,%3};"
                 : "+f"(c[0]), "+f"(c[1]), "+f"(c[2]), "+f"(c[3])
                 : "r"(a[0]), "r"(a[1]), "r"(a[2]), "r"(a[3]), "r"(b0), "r"(b1));
}
__device__ __forceinline__ float4 ld_cg4(const float* p) {
    float4 v;
    asm volatile("ld.global.cg.v4.f32 {%0,%1,%2,%3}, [%4];"
                 : "=f"(v.x), "=f"(v.y), "=f"(v.z), "=f"(v.w) : "l"(p));
    return v;
}

// ---------------- prepass: hi/lo bf16 splits --------------------------------
__global__ void split_x_kernel(const float* __restrict__ x) {
    size_t fi = (size_t)blockIdx.x * blockDim.x + threadIdx.x;
    if (fi >= (size_t)B_ * T_ * H_ / 4) return;
    float4 v = *(const float4*)(x + fi * 4);
    union { __nv_bfloat16 b[4]; uint2 u; } hh, ll;
    float f[4] = {v.x, v.y, v.z, v.w};
#pragma unroll
    for (int i = 0; i < 4; i++) {
        hh.b[i] = __float2bfloat16_rn(f[i]);
        ll.b[i] = __float2bfloat16_rn(f[i] - __bfloat162float(hh.b[i]));
    }
    *(uint2*)(g_xh + fi * 4) = hh.u;
    *(uint2*)(g_xl + fi * 4) = ll.u;
}

__global__ void split_w_kernel(const float* __restrict__ W) {
    size_t fi = (size_t)blockIdx.x * blockDim.x + threadIdx.x;
    if (fi >= (size_t)H_ * H_ / 4) return;
    int g = (int)(fi >> 9);
    int c = (int)(fi & 511) * 4;
    const float* base = W + (size_t)g * WLD;

    float4 v = *(const float4*)(base + c);
    union { __nv_bfloat16 b[4]; uint2 u; } hh, ll;
    float f[4] = {v.x, v.y, v.z, v.w};
#pragma unroll
    for (int i = 0; i < 4; i++) {
        hh.b[i] = __float2bfloat16_rn(f[i]);
        ll.b[i] = __float2bfloat16_rn(f[i] - __bfloat162float(hh.b[i]));
    }
    *(uint2*)(g_wxh + (size_t)g * H_ + c) = hh.u;
    *(uint2*)(g_wxl + (size_t)g * H_ + c) = ll.u;

    v = *(const float4*)(base + H_ + c);
    float f2[4] = {v.x, v.y, v.z, v.w};
#pragma unroll
    for (int i = 0; i < 4; i++) {
        hh.b[i] = __float2bfloat16_rn(f2[i]);
        ll.b[i] = __float2bfloat16_rn(f2[i] - __bfloat162float(hh.b[i]));
    }
    *(uint2*)(g_whh + (size_t)g * H_ + c) = hh.u;
    *(uint2*)(g_whl + (size_t)g * H_ + c) = ll.u;
}

// ===========================================================================
// Phase 1: u[m,g] = sum_k x[m,k] W[g,k] + b[g], 3x bf16 split mma.
// 128x128x32 tiles, 4-stage cp.async pipeline.
// ===========================================================================
#define P1_ST 40
#define P1_TILE (128 * P1_ST)
#define P1_NS 4
#define P1_SMEM_BYTES (2 * P1_NS * P1_TILE * 2)   // 81920

__global__ __launch_bounds__(256, 2)
void gemm_u_mma(const float* __restrict__ bias, float* __restrict__ out)
{
    extern __shared__ __align__(16) __nv_bfloat16 sm[];
    __nv_bfloat16* As[P1_NS];
    __nv_bfloat16* Bs[P1_NS];
#pragma unroll
    for (int s = 0; s < P1_NS; s++) {
        As[s] = sm + s * P1_TILE;
        Bs[s] = sm + (P1_NS + s) * P1_TILE;
    }

    const int tid = threadIdx.x, lane = tid & 31, wid = tid >> 5;
    const int m0 = blockIdx.y * 128, g0 = blockIdx.x * 128;
    const int wm = wid & 3, wn = wid >> 2;

    const __nv_bfloat16* Ag[3] = { g_xh, g_xh, g_xl };
    const __nv_bfloat16* Bg[3] = { g_wxh, g_wxl, g_wxh };

    const int lrow = tid >> 1;
    const int lco  = (tid & 1) * 16;

    float acc[2][8][4];
#pragma unroll
    for (int i = 0; i < 2; i++)
#pragma unroll
        for (int j = 0; j < 8; j++)
#pragma unroll
            for (int q = 0; q < 4; q++) acc[i][j][q] = 0.0f;

#define P1_ISSUE(st, it) do {                                                  \
        int _p = (it) >> 6, _kk = ((it) & 63) * 32;                            \
        const __nv_bfloat16* _ga = Ag[_p] + (size_t)(m0 + lrow) * H_ + _kk + lco; \
        const __nv_bfloat16* _gb = Bg[_p] + (size_t)(g0 + lrow) * H_ + _kk + lco; \
        uint32_t _sa = smem_u32(As[st] + lrow * P1_ST + lco);                  \
        uint32_t _sb = smem_u32(Bs[st] + lrow * P1_ST + lco);                  \
        cp16(_sa, _ga); cp16(_sa + 16, _ga + 8);                               \
        cp16(_sb, _gb); cp16(_sb + 16, _gb + 8);                               \
    } while (0)

    P1_ISSUE(0, 0); CP_COMMIT();
    P1_ISSUE(1, 1); CP_COMMIT();
    P1_ISSUE(2, 2); CP_COMMIT();

    const int NT = 192;
    for (int it = 0; it < NT; ++it) {
        asm volatile("cp.async.wait_group 2;");
        __syncthreads();
        int nx = it + 3;
        if (nx < NT) { P1_ISSUE(nx & 3, nx); }
        CP_COMMIT();

        const __nv_bfloat16* A_s = As[it & 3];
        const __nv_bfloat16* B_s = Bs[it & 3];
#pragma unroll
        for (int kq = 0; kq < 2; kq++) {
            uint32_t a[2][4];
#pragma unroll
            for (int mt = 0; mt < 2; mt++)
                ldsm4(a[mt], smem_u32(A_s + (wm * 32 + mt * 16 + (lane & 15)) * P1_ST
                                          + kq * 16 + ((lane >> 4) << 3)));
            uint32_t bf[4][4];
#pragma unroll
            for (int ng = 0; ng < 4; ng++)
                ldsm4(bf[ng], smem_u32(B_s + (wn * 64 + ng * 16 + (lane & 7) + ((lane & 16) >> 1)) * P1_ST
                                           + kq * 16 + (lane & 8)));
#pragma unroll
            for (int mt = 0; mt < 2; mt++)
#pragma unroll
                for (int ng = 0; ng < 4; ng++) {
                    mma16816(acc[mt][2 * ng],     a[mt], bf[ng][0], bf[ng][1]);
                    mma16816(acc[mt][2 * ng + 1], a[mt], bf[ng][2], bf[ng][3]);
                }
        }
    }

    const int r0 = lane >> 2, c0 = (lane & 3) * 2;
#pragma unroll
    for (int mt = 0; mt < 2; mt++) {
        int m = m0 + wm * 32 + mt * 16 + r0;
#pragma unroll
        for (int nt = 0; nt < 8; nt++) {
            int g = g0 + wn * 64 + nt * 8 + c0;
            float bx = bias[g], by = bias[g + 1];
            float2 v0 = { acc[mt][nt][0] + bx, acc[mt][nt][1] + by };
            float2 v1 = { acc[mt][nt][2] + bx, acc[mt][nt][3] + by };
            *(float2*)(out + (size_t)m * H_ + g)       = v0;
            *(float2*)(out + (size_t)(m + 8) * H_ + g) = v1;
        }
    }
}

// ===========================================================================
// Phase 2: persistent scan. h_t[b,g] = u_t[b,g] + sum_k h_{t-1}[b,k] Wh[g,k]
// Grid 128 = 32 g-tiles (64) x 4 k-tiles (512). Wh hi/lo slice in smem.
// Warp w owns n=8 g-cols, full K=512: no intra-block reduction.
// Per step: load h k-slice (16x512 fp32) -> split bf16 hi/lo in smem ->
// 16 unrolled k32 chunks of ldsm+mma -> 4 atomicAdds/thread -> barrier.
// ===========================================================================
#define GT 64
#define KT 512
#define WST 520                         // Wh smem row stride (bf16)
#define HST 520                         // h  smem row stride (bf16)
#define O_WHH 0
#define O_WHL (GT * WST)                // 33280
#define O_HH  (2 * GT * WST)            // 66560
#define O_HL  (O_HH + B_ * HST)         // 74880
#define SC_SMEM_ELEMS (O_HL + B_ * HST) // 83200
#define SC_SMEM_BYTES (SC_SMEM_ELEMS * 2)  // 166400

__global__ __launch_bounds__(256, 1)
void rnn_scan3(float* __restrict__ out)
{
    extern __shared__ __align__(16) __nv_bfloat16 sm[];
    __nv_bfloat16* whh_s = sm + O_WHH;
    __nv_bfloat16* whl_s = sm + O_WHL;
    __nv_bfloat16* hh_s  = sm + O_HH;
    __nv_bfloat16* hl_s  = sm + O_HL;

    const int tid = threadIdx.x, lane = tid & 31, wid = tid >> 5;
    const int gi = blockIdx.x & 31;     // 32 g-tiles
    const int ki = blockIdx.x >> 5;     // 4 k-tiles
    const int g0 = gi * GT;
    const int k0 = ki * KT;

    // ---- stage Wh hi/lo slice: 64 g-rows x 512 k ----
    for (int i = tid; i < GT * (KT / 8); i += 256) {
        int row = i >> 6;               // 0..63
        int c8  = (i & 63) * 8;
        *(uint4*)(whh_s + row * WST + c8) =
            *(const uint4*)(g_whh + (size_t)(g0 + row) * H_ + k0 + c8);
        *(uint4*)(whl_s + row * WST + c8) =
            *(const uint4*)(g_whl + (size_t)(g0 + row) * H_ + k0 + c8);
    }
    __syncthreads();

    // warp owns 8 g-cols
    const int n0w = wid * 8;
    const int r0 = lane >> 2, c0 = (lane & 3) * 2;

    // ldsm bases (fixed strides; advance by chunk)
    const uint32_t aHb = smem_u32(hh_s + (lane & 15) * HST + ((lane >> 4) << 3));
    const uint32_t aLb = smem_u32(hl_s + (lane & 15) * HST + ((lane >> 4) << 3));
    const int brow = n0w + (lane & 7);
    const int bcol = ((lane >> 3) & 3) * 8;     // k-offsets 0,8,16,24 (x4 = 2 k-iters)
    const uint32_t bHb = smem_u32(whh_s + brow * WST + bcol);
    const uint32_t bLb = smem_u32(whl_s + brow * WST + bcol);

    for (int t = 1; t < T_; ++t) {
        // ---- load h_{t-1} k-slice (16 x 512 fp32), split into smem ----
#pragma unroll
        for (int r = 0; r < 8; r++) {
            int fi = tid + r * 256;                 // float4 idx 0..2047
            int b  = fi >> 7;                       // 0..15
            int c4 = fi & 127;                      // float4 within row
            float4 h4 = ld_cg4(out + (size_t)b * TH_ + (size_t)(t - 1) * H_ + k0 + c4 * 4);
            union { __nv_bfloat16 bb[4]; uint2 u; } th, tl;
            float f[4] = {h4.x, h4.y, h4.z, h4.w};
#pragma unroll
            for (int q = 0; q < 4; q++) {
                th.bb[q] = __float2bfloat16_rn(f[q]);
                tl.bb[q] = __float2bfloat16_rn(f[q] - __bfloat162float(th.bb[q]));
            }
            *(uint2*)(hh_s + b * HST + c4 * 4) = th.u;
            *(uint2*)(hl_s + b * HST + c4 * 4) = tl.u;
        }
        __syncthreads();

        // ---- compute: 16 k32 chunks, 3 accumulators ----
        float acc0[4], acc1[4], acc2[4];
#pragma unroll
        for (int q = 0; q < 4; q++) { acc0[q] = 0.0f; acc1[q] = 0.0f; acc2[q] = 0.0f; }

#pragma unroll
        for (int kc = 0; kc < 16; kc++) {
            const uint32_t off = kc * 64;           // 32 bf16 = 64 bytes
            uint32_t ah0[4], ah1[4], al0[4], al1[4], bh[4], bl[4];
            ldsm4(bh,  bHb + off);
            ldsm4(ah0, aHb + off);
            ldsm4(ah1, aHb + off + 32);
            ldsm4(bl,  bLb + off);
            ldsm4(al0, aLb + off);
            ldsm4(al1, aLb + off + 32);
            mma16816(acc0, ah0, bh[0], bh[1]);
            mma16816(acc1, ah0, bl[0], bl[1]);
            mma16816(acc2, al0, bh[0], bh[1]);
            mma16816(acc0, ah1, bh[2], bh[3]);
            mma16816(acc1, ah1, bl[2], bl[3]);
            mma16816(acc2, al1, bh[2], bh[3]);
        }

        // ---- epilogue: 4 atomic adds into out[:, t, :] (holds u_t) ----
#pragma unroll
        for (int q = 0; q < 4; q++) acc0[q] += acc1[q] + acc2[q];
        {
            float* p0 = out + (size_t)r0 * TH_ + (size_t)t * H_ + g0 + n0w + c0;
            atomicAdd(p0,     acc0[0]);
            atomicAdd(p0 + 1, acc0[1]);
            float* p1 = out + (size_t)(r0 + 8) * TH_ + (size_t)t * H_ + g0 + n0w + c0;
            atomicAdd(p1,     acc0[2]);
            atomicAdd(p1 + 1, acc0[3]);
        }

        // ---- global step barrier ----
        __threadfence();
        __syncthreads();
        if (t < T_ - 1) {
            if (tid == 0) {
                atomicAdd(&g_bar[t], 1u);
                volatile unsigned* p = &g_bar[t];
                while (*p < NBLK) { __nanosleep(32); }
                __threadfence();
            }
            __syncthreads();
        }
    }
}

// ---------------- h_last copy ----------------------------------------------
__global__ void hlast_kernel(const float* __restrict__ out,
                             float* __restrict__ hlast)
{
    int i = blockIdx.x * blockDim.x + threadIdx.x;
    if (i < B_ * H_) {
        int b = i / H_;
        int g = i % H_;
        hlast[i] = out[(size_t)b * TH_ + (size_t)(T_ - 1) * H_ + g];
    }
}

// ---------------- launch ----------------------------------------------------
extern "C" void kernel_launch(void* const* d_in, const int* in_sizes, int n_in,
                              void* d_out, int out_size)
{
    const float* x  = (const float*)d_in[0];
    const float* W  = (const float*)d_in[1];
    const float* bi = (const float*)d_in[2];
    float* out = (float*)d_out;

    cudaFuncSetAttribute(gemm_u_mma,
                         cudaFuncAttributeMaxDynamicSharedMemorySize,
                         P1_SMEM_BYTES);
    cudaFuncSetAttribute(rnn_scan3,
                         cudaFuncAttributeMaxDynamicSharedMemorySize,
                         SC_SMEM_BYTES);

    zero_bar_kernel<<<1, T_>>>();
    split_x_kernel<<<(B_ * T_ * H_ / 4 + 255) / 256, 256>>>(x);
    split_w_kernel<<<(H_ * H_ / 4 + 255) / 256, 256>>>(W);

    dim3 ggrid(H_ / 128, (B_ * T_) / 128);   // (16, 64)
    gemm_u_mma<<<ggrid, 256, P1_SMEM_BYTES>>>(bi, out);

    rnn_scan3<<<NBLK, 256, SC_SMEM_BYTES>>>(out);

    if (out_size >= B_ * T_ * H_ + B_ * H_) {
        hlast_kernel<<<(B_ * H_ + 255) / 256, 256>>>(out, out + (size_t)B_ * T_ * H_);
    }
}